// round 13
// baseline (speedup 1.0000x reference)
#include <cuda_runtime.h>
#include <math.h>

// Problem constants
#define B_      32
#define C_IN    8
#define C_OUT   16
#define H_      512
#define W_      512
#define KK      3
#define PLANES  (B_ * C_IN)            // 256
#define PLANE_ELEMS (H_ * W_)          // 262144
#define BPP     8                      // blocks per plane (finer tail quantization)
#define NBLOCKS (PLANES * BPP)         // 2048
#define NTHREADS 256
#define CHUNK_F4 (PLANE_ELEMS / 4 / BPP)  // 8192 float4 per block (32/thread)
#define AREA    264196.0f              // (H+K-1)^2 = 514^2

// Partial sums scratch: NBLOCKS floats, fully overwritten every launch.
__device__ float g_partial[NBLOCKS];

__global__ void __launch_bounds__(NTHREADS) reduce_planes_kernel(const float4* __restrict__ x) {
    const int blk   = blockIdx.x;
    const int plane = blk / BPP;
    const int sub   = blk % BPP;
    const float4* p = x + (size_t)plane * (PLANE_ELEMS / 4) + (size_t)sub * CHUNK_F4;

    float s = 0.0f;
    // 8192 float4 / 256 threads = 32 per thread; unroll-8 batches 8 LDG.128
    // per thread (proven MLP sweet spot). .cs = evict-first: once-through data.
    #pragma unroll 8
    for (int i = threadIdx.x; i < CHUNK_F4; i += NTHREADS) {
        float4 v = __ldcs(&p[i]);
        s += (v.x + v.y) + (v.z + v.w);
    }

    // warp reduce
    #pragma unroll
    for (int off = 16; off > 0; off >>= 1)
        s += __shfl_xor_sync(0xFFFFFFFFu, s, off);

    __shared__ float warp_sums[NTHREADS / 32];
    const int lane = threadIdx.x & 31;
    const int wid  = threadIdx.x >> 5;
    if (lane == 0) warp_sums[wid] = s;
    __syncthreads();

    if (wid == 0) {
        float t = (lane < NTHREADS / 32) ? warp_sums[lane] : 0.0f;
        #pragma unroll
        for (int off = 4; off > 0; off >>= 1)
            t += __shfl_xor_sync(0xFFFFFFFFu, t, off);
        if (lane == 0) g_partial[blk] = t;
    }
}

__global__ void __launch_bounds__(256) finalize_kernel(const float* __restrict__ w,
                                                       const float* __restrict__ bias,
                                                       float* __restrict__ out) {
    __shared__ float Sx[B_][C_IN];     // per-(n,ci) full plane sums
    __shared__ float Sw[C_OUT][C_IN];  // per-(co,ci) kernel-tap sums
    __shared__ float Sb[C_OUT];

    const int t = threadIdx.x;

    // All independent global loads issued up front (latency overlap).
    if (t < PLANES) {
        const float4* pp = reinterpret_cast<const float4*>(&g_partial[t * BPP]);
        const float4 a = pp[0];
        const float4 b = pp[1];
        Sx[t / C_IN][t % C_IN] =
            ((a.x + a.y) + (a.z + a.w)) + ((b.x + b.y) + (b.z + b.w));
    }
    if (t < C_OUT * C_IN) {
        const float* wp = w + t * (KK * KK);
        float ws = 0.0f;
        #pragma unroll
        for (int k = 0; k < KK * KK; k++) ws += wp[k];
        Sw[t / C_IN][t % C_IN] = ws;
    }
    if (t < C_OUT) Sb[t] = bias[t];
    __syncthreads();

    if (t < B_) {
        const float inv_area = 1.0f / AREA;
        float pooled[C_OUT];
        float mx = -INFINITY;
        #pragma unroll
        for (int co = 0; co < C_OUT; co++) {
            float d = 0.0f;
            #pragma unroll
            for (int ci = 0; ci < C_IN; ci++)
                d = fmaf(Sx[t][ci], Sw[co][ci], d);
            float v = d * inv_area + Sb[co];
            pooled[co] = v;
            mx = fmaxf(mx, v);
        }
        float se = 0.0f;
        #pragma unroll
        for (int co = 0; co < C_OUT; co++)
            se += __expf(pooled[co] - mx);
        out[t] = (mx + logf(se)) * 10.0f;
    }
}

extern "C" void kernel_launch(void* const* d_in, const int* in_sizes, int n_in,
                              void* d_out, int out_size) {
    const float4* x    = (const float4*)d_in[0];  // (32,8,512,512) fp32
    const float*  w    = (const float*)d_in[1];   // (16,8,3,3) fp32
    const float*  bias = (const float*)d_in[2];   // (16,1,1) fp32
    float* out = (float*)d_out;                   // (32,) fp32

    reduce_planes_kernel<<<NBLOCKS, NTHREADS>>>(x);
    finalize_kernel<<<1, 256>>>(w, bias, out);
}

// round 14
// speedup vs baseline: 1.0485x; 1.0485x over previous
#include <cuda_runtime.h>
#include <math.h>

// Problem constants
#define B_      32
#define C_IN    8
#define C_OUT   16
#define H_      512
#define W_      512
#define KK      3
#define PLANES  (B_ * C_IN)            // 256
#define PLANE_ELEMS (H_ * W_)          // 262144
#define BPP     4                      // blocks per plane (measured-best geometry)
#define NBLOCKS (PLANES * BPP)         // 1024
#define NTHREADS 256
#define CHUNK_F4 (PLANE_ELEMS / 4 / BPP)  // 16384 float4 per block
#define AREA    264196.0f              // (H+K-1)^2 = 514^2

// Partial sums scratch: NBLOCKS floats, fully overwritten every launch.
__device__ float g_partial[NBLOCKS];

__global__ void __launch_bounds__(NTHREADS) reduce_planes_kernel(const float4* __restrict__ x) {
    const int blk   = blockIdx.x;
    const int plane = blk / BPP;
    const int sub   = blk % BPP;
    const float4* p = x + (size_t)plane * (PLANE_ELEMS / 4) + (size_t)sub * CHUNK_F4;

    float s = 0.0f;
    // 16384 float4 / 256 threads = 64 per thread; unroll-8 batches 8 LDG.128
    // per thread (proven MLP sweet spot). .cs = evict-first: once-through data.
    #pragma unroll 8
    for (int i = threadIdx.x; i < CHUNK_F4; i += NTHREADS) {
        float4 v = __ldcs(&p[i]);
        s += (v.x + v.y) + (v.z + v.w);
    }

    // warp reduce
    #pragma unroll
    for (int off = 16; off > 0; off >>= 1)
        s += __shfl_xor_sync(0xFFFFFFFFu, s, off);

    __shared__ float warp_sums[NTHREADS / 32];
    const int lane = threadIdx.x & 31;
    const int wid  = threadIdx.x >> 5;
    if (lane == 0) warp_sums[wid] = s;
    __syncthreads();

    if (wid == 0) {
        float t = (lane < NTHREADS / 32) ? warp_sums[lane] : 0.0f;
        #pragma unroll
        for (int off = 4; off > 0; off >>= 1)
            t += __shfl_xor_sync(0xFFFFFFFFu, t, off);
        if (lane == 0) g_partial[blk] = t;
    }
}

__global__ void __launch_bounds__(256) finalize_kernel(const float* __restrict__ w,
                                                       const float* __restrict__ bias,
                                                       float* __restrict__ out) {
    __shared__ float Sx[B_][C_IN];     // per-(n,ci) full plane sums
    __shared__ float Sw[C_OUT][C_IN];  // per-(co,ci) kernel-tap sums
    __shared__ float Sb[C_OUT];

    const int t = threadIdx.x;

    // Weights/bias are independent of the reduce kernel — load during the
    // upstream grid's drain (PDL window).
    float ws = 0.0f;
    if (t < C_OUT * C_IN) {
        const float* wp = w + t * (KK * KK);
        #pragma unroll
        for (int k = 0; k < KK * KK; k++) ws += wp[k];
    }
    float bv = (t < C_OUT) ? bias[t] : 0.0f;

    // Wait for the reduce grid to complete (g_partial visible afterwards).
    cudaGridDependencySynchronize();

    if (t < PLANES) {
        const float4 pv = *reinterpret_cast<const float4*>(&g_partial[t * BPP]);
        Sx[t / C_IN][t % C_IN] = (pv.x + pv.y) + (pv.z + pv.w);
    }
    if (t < C_OUT * C_IN) Sw[t / C_IN][t % C_IN] = ws;
    if (t < C_OUT) Sb[t] = bv;
    __syncthreads();

    if (t < B_) {
        const float inv_area = 1.0f / AREA;
        float pooled[C_OUT];
        float mx = -INFINITY;
        #pragma unroll
        for (int co = 0; co < C_OUT; co++) {
            float d = 0.0f;
            #pragma unroll
            for (int ci = 0; ci < C_IN; ci++)
                d = fmaf(Sx[t][ci], Sw[co][ci], d);
            float v = d * inv_area + Sb[co];
            pooled[co] = v;
            mx = fmaxf(mx, v);
        }
        float se = 0.0f;
        #pragma unroll
        for (int co = 0; co < C_OUT; co++)
            se += __expf(pooled[co] - mx);
        out[t] = (mx + logf(se)) * 10.0f;
    }
}

extern "C" void kernel_launch(void* const* d_in, const int* in_sizes, int n_in,
                              void* d_out, int out_size) {
    const float4* x    = (const float4*)d_in[0];  // (32,8,512,512) fp32
    const float*  w    = (const float*)d_in[1];   // (16,8,3,3) fp32
    const float*  bias = (const float*)d_in[2];   // (16,1,1) fp32
    float* out = (float*)d_out;                   // (32,) fp32

    reduce_planes_kernel<<<NBLOCKS, NTHREADS>>>(x);

    // Finalize with programmatic dependent launch: node dispatch overlaps the
    // reduce tail; correctness preserved by cudaGridDependencySynchronize().
    cudaLaunchConfig_t cfg = {};
    cfg.gridDim  = dim3(1, 1, 1);
    cfg.blockDim = dim3(256, 1, 1);
    cfg.dynamicSmemBytes = 0;
    cfg.stream = 0;
    cudaLaunchAttribute attr[1];
    attr[0].id = cudaLaunchAttributeProgrammaticStreamSerialization;
    attr[0].val.programmaticStreamSerializationAllowed = 1;
    cfg.attrs = attr;
    cfg.numAttrs = 1;
    cudaLaunchKernelEx(&cfg, finalize_kernel, w, bias, out);
}

// round 15
// speedup vs baseline: 1.0493x; 1.0007x over previous
#include <cuda_runtime.h>
#include <math.h>

// Problem constants
#define B_      32
#define C_IN    8
#define C_OUT   16
#define H_      512
#define W_      512
#define KK      3
#define PLANES  (B_ * C_IN)            // 256
#define PLANE_ELEMS (H_ * W_)          // 262144
#define BPP     4                      // blocks per plane (measured-best geometry)
#define NBLOCKS (PLANES * BPP)         // 1024
#define NTHREADS 256
#define CHUNK_F4 (PLANE_ELEMS / 4 / BPP)  // 16384 float4 per block
#define AREA    264196.0f              // (H+K-1)^2 = 514^2

// Partial sums scratch: NBLOCKS floats, fully overwritten every launch.
__device__ float g_partial[NBLOCKS];

__global__ void __launch_bounds__(NTHREADS) reduce_planes_kernel(const float4* __restrict__ x) {
    // Open the PDL window immediately: the dependent finalize kernel may
    // launch and run its independent preloads during our entire stream.
    // It gridDependencySynchronize()s before touching g_partial.
    cudaTriggerProgrammaticLaunchCompletion();

    const int blk   = blockIdx.x;
    const int plane = blk / BPP;
    const int sub   = blk % BPP;
    const float4* p = x + (size_t)plane * (PLANE_ELEMS / 4) + (size_t)sub * CHUNK_F4;

    float s = 0.0f;
    // 16384 float4 / 256 threads = 64 per thread; unroll-8 batches 8 LDG.128
    // per thread (proven MLP sweet spot). .cs = evict-first: once-through data.
    #pragma unroll 8
    for (int i = threadIdx.x; i < CHUNK_F4; i += NTHREADS) {
        float4 v = __ldcs(&p[i]);
        s += (v.x + v.y) + (v.z + v.w);
    }

    // warp reduce
    #pragma unroll
    for (int off = 16; off > 0; off >>= 1)
        s += __shfl_xor_sync(0xFFFFFFFFu, s, off);

    __shared__ float warp_sums[NTHREADS / 32];
    const int lane = threadIdx.x & 31;
    const int wid  = threadIdx.x >> 5;
    if (lane == 0) warp_sums[wid] = s;
    __syncthreads();

    if (wid == 0) {
        float t = (lane < NTHREADS / 32) ? warp_sums[lane] : 0.0f;
        #pragma unroll
        for (int off = 4; off > 0; off >>= 1)
            t += __shfl_xor_sync(0xFFFFFFFFu, t, off);
        if (lane == 0) g_partial[blk] = t;
    }
}

__global__ void __launch_bounds__(256) finalize_kernel(const float* __restrict__ w,
                                                       const float* __restrict__ bias,
                                                       float* __restrict__ out) {
    __shared__ float Sx[B_][C_IN];     // per-(n,ci) full plane sums
    __shared__ float Sw[C_OUT][C_IN];  // per-(co,ci) kernel-tap sums
    __shared__ float Sb[C_OUT];

    const int t = threadIdx.x;

    // Weights/bias are independent of the reduce kernel — load during the
    // upstream grid's execution (PDL window).
    float ws = 0.0f;
    if (t < C_OUT * C_IN) {
        const float* wp = w + t * (KK * KK);
        #pragma unroll
        for (int k = 0; k < KK * KK; k++) ws += wp[k];
    }
    float bv = (t < C_OUT) ? bias[t] : 0.0f;

    // Wait for the reduce grid to complete (g_partial visible afterwards).
    cudaGridDependencySynchronize();

    if (t < PLANES) {
        const float4 pv = *reinterpret_cast<const float4*>(&g_partial[t * BPP]);
        Sx[t / C_IN][t % C_IN] = (pv.x + pv.y) + (pv.z + pv.w);
    }
    if (t < C_OUT * C_IN) Sw[t / C_IN][t % C_IN] = ws;
    if (t < C_OUT) Sb[t] = bv;
    __syncthreads();

    if (t < B_) {
        const float inv_area = 1.0f / AREA;
        float pooled[C_OUT];
        float mx = -INFINITY;
        #pragma unroll
        for (int co = 0; co < C_OUT; co++) {
            float d = 0.0f;
            #pragma unroll
            for (int ci = 0; ci < C_IN; ci++)
                d = fmaf(Sx[t][ci], Sw[co][ci], d);
            float v = d * inv_area + Sb[co];
            pooled[co] = v;
            mx = fmaxf(mx, v);
        }
        float se = 0.0f;
        #pragma unroll
        for (int co = 0; co < C_OUT; co++)
            se += __expf(pooled[co] - mx);
        out[t] = (mx + logf(se)) * 10.0f;
    }
}

extern "C" void kernel_launch(void* const* d_in, const int* in_sizes, int n_in,
                              void* d_out, int out_size) {
    const float4* x    = (const float4*)d_in[0];  // (32,8,512,512) fp32
    const float*  w    = (const float*)d_in[1];   // (16,8,3,3) fp32
    const float*  bias = (const float*)d_in[2];   // (16,1,1) fp32
    float* out = (float*)d_out;                   // (32,) fp32

    reduce_planes_kernel<<<NBLOCKS, NTHREADS>>>(x);

    // Finalize with programmatic dependent launch: dispatch + preloads overlap
    // the reduce stream; correctness preserved by cudaGridDependencySynchronize().
    cudaLaunchConfig_t cfg = {};
    cfg.gridDim  = dim3(1, 1, 1);
    cfg.blockDim = dim3(256, 1, 1);
    cfg.dynamicSmemBytes = 0;
    cfg.stream = 0;
    cudaLaunchAttribute attr[1];
    attr[0].id = cudaLaunchAttributeProgrammaticStreamSerialization;
    attr[0].val.programmaticStreamSerializationAllowed = 1;
    cfg.attrs = attr;
    cfg.numAttrs = 1;
    cudaLaunchKernelEx(&cfg, finalize_kernel, w, bias, out);
}